// round 12
// baseline (speedup 1.0000x reference)
#include <cuda_runtime.h>
#include <stdint.h>

// Problem constants: D=64, M=32, output fp32 [n_seg, 2]
#define DIM      64
#define MLEN     32
#define DC       2                      // d-rows per chunk
#define NCHUNK   (DIM / DC)             // 32
#define TPB      256
#define KPOS     8                      // positions per thread
#define TILE_POS (TPB * KPOS)           // 2048 window starts per block
#define TILE_COLS (TILE_POS + MLEN)     // 2080 columns per tile row
#define NGRAN    (TILE_COLS / 4)        // 520 16B granules per row
// pad 1 granule (16B) per 8 granules (128B): conflict-free for stride-2-granule lanes
#define RSTRIDE  (TILE_COLS + (TILE_COLS / 32) * 4)   // 2340 floats

#define MAX_SEG  8192

__device__ unsigned g_mins[MAX_SEG];
__device__ int g_done;
__device__ unsigned long long g_q2[DIM * MLEN];    // staging for duplicated q pairs
__constant__ unsigned long long c_q2[DIM * MLEN];  // (v,v) pairs on the constant port

// order-preserving float -> uint mapping (ascending)
__device__ __forceinline__ unsigned enc_f(float f) {
    int b = __float_as_int(f);
    return (unsigned)(b >= 0 ? (b | 0x80000000) : ~b);
}
__device__ __forceinline__ float dec_f(unsigned u) {
    int b = (u & 0x80000000u) ? (int)(u & 0x7FFFFFFFu) : ~(int)u;
    return __int_as_float(b);
}

__device__ __forceinline__ unsigned long long ffma2(unsigned long long a,
                                                    unsigned long long b,
                                                    unsigned long long c) {
    unsigned long long d;
    asm("fma.rn.f32x2 %0, %1, %2, %3;" : "=l"(d) : "l"(a), "l"(b), "l"(c));
    return d;
}
__device__ __forceinline__ unsigned long long pk2(float lo, float hi) {
    unsigned long long r;
    asm("mov.b64 %0, {%1, %2};" : "=l"(r) : "f"(lo), "f"(hi));
    return r;
}
__device__ __forceinline__ void up2(unsigned long long v, float& a, float& b) {
    asm("mov.b64 {%0, %1}, %2;" : "=f"(a), "=f"(b) : "l"(v));
}
__device__ __forceinline__ void cpa16(uint32_t dst, const void* src) {
    asm volatile("cp.async.cg.shared.global [%0], [%1], 16;" :: "r"(dst), "l"(src));
}
__device__ __forceinline__ void cpa_commit() {
    asm volatile("cp.async.commit_group;" ::: "memory");
}
__device__ __forceinline__ void cpa_wait1() {
    asm volatile("cp.async.wait_group 1;" ::: "memory");
}

__global__ void init_mins_kernel(int n) {
    int i = blockIdx.x * blockDim.x + threadIdx.x;
    if (i < n) g_mins[i] = 0xFFFFFFFFu;
}

// stage duplicated query pairs: e = d*32 + h*16 + kind*8 + t2
//   value = q[d*MLEN + 16*h + 2*t2 + kind], duplicated into both lanes
__global__ void prep_q_kernel(const float* __restrict__ q) {
    int e = blockIdx.x * blockDim.x + threadIdx.x;
    if (e < DIM * MLEN) {
        int d    = e >> 5;
        int rem  = e & 31;
        int h    = rem >> 4;
        int kind = (rem >> 3) & 1;
        int t2   = rem & 7;
        float v = q[d * MLEN + 16 * h + 2 * t2 + kind];
        g_q2[e] = pk2(v, v);
    }
}

// smem float layout:
//   tile : [2][DC][RSTRIDE]          floats 0 .. 9360
//   s_sh : [RSTRIDE]                 floats 9360 .. 11700
#define SM_SSH   (2 * DC * RSTRIDE)
#define SM_TOTAL ((SM_SSH + RSTRIDE) * 4)

__global__ __launch_bounds__(TPB, 4) void shapelet_main_kernel(
    const float* __restrict__ X,      // [DIM, T]
    const int*   __restrict__ cum,    // [n_seg+1]
    const float* __restrict__ lin_w,
    const float* __restrict__ lin_b,
    float* __restrict__ out,
    int T, int n_seg, int P)
{
    extern __shared__ float sh[];
    float* s_sh = sh + SM_SSH;
    const uint32_t sbase = (uint32_t)__cvta_generic_to_shared(sh);

    const int tid    = threadIdx.x;
    const int pStart = blockIdx.x * TILE_POS;
    const bool inb   = (pStart + TILE_COLS <= T);

    unsigned long long accE[4], accO[5], sq[4];
#pragma unroll
    for (int a = 0; a < 4; ++a) { accE[a] = 0ull; sq[a] = 0ull; }
#pragma unroll
    for (int a = 0; a < 5; ++a) accO[a] = 0ull;
    float tacc = 0.f;                       // tail col (warp 0 only)
    const int tailpc = (2048 + tid) + (((2048 + tid) >> 5) << 2);

    // ---- prefetch one chunk into buffer b ----
    auto prefetch = [&](int dc, int b) {
#pragma unroll
        for (int r = 0; r < DC; ++r) {
            const float* src = X + (size_t)(dc * DC + r) * T + pStart;
            uint32_t drow = sbase + (uint32_t)((b * DC + r) * RSTRIDE) * 4u;
            float* growp = sh + (b * DC + r) * RSTRIDE;
            if (inb) {
                for (int gi = tid; gi < NGRAN; gi += TPB) {
                    int pf = (gi + (gi >> 3)) << 2;
                    cpa16(drow + (uint32_t)pf * 4u, src + (gi << 2));
                }
            } else {
                for (int gi = tid; gi < NGRAN; gi += TPB) {
                    int pf = (gi + (gi >> 3)) << 2;
                    int gc = pStart + (gi << 2);
                    if (gc + 4 <= T) {
                        cpa16(drow + (uint32_t)pf * 4u, src + (gi << 2));
                    } else {
                        float4 z;
                        z.x = (gc + 0 < T) ? src[(gi << 2) + 0] : 0.f;
                        z.y = (gc + 1 < T) ? src[(gi << 2) + 1] : 0.f;
                        z.z = (gc + 2 < T) ? src[(gi << 2) + 2] : 0.f;
                        z.w = (gc + 3 < T) ? src[(gi << 2) + 3] : 0.f;
                        *(float4*)(growp + pf) = z;
                    }
                }
            }
        }
    };

    prefetch(0, 0);
    cpa_commit();

#pragma unroll 1
    for (int dc = 0; dc < NCHUNK; ++dc) {
        const int par = dc & 1;
        if (dc + 1 < NCHUNK) prefetch(dc + 1, (dc + 1) & 1);
        cpa_commit();
        cpa_wait1();
        __syncthreads();

        const float* tb = sh + par * DC * RSTRIDE;
#pragma unroll
        for (int r = 0; r < DC; ++r) {
            const float* rowp = tb + r * RSTRIDE;
#pragma unroll
            for (int h = 0; h < 2; ++h) {
                unsigned long long xq[12];
#pragma unroll
                for (int i = 0; i < 6; ++i) {
                    int g = 2 * tid + 4 * h + i;
                    int pf = (g + (g >> 3)) << 2;
                    ulonglong2 vv = *(const ulonglong2*)(rowp + pf);
                    xq[2 * i] = vv.x; xq[2 * i + 1] = vv.y;
                }
                if (h == 0) {
#pragma unroll
                    for (int j = 0; j < 4; ++j)
                        sq[j] = ffma2(xq[j], xq[j], sq[j]);
                }
                // pre-duplicated query pairs straight off the constant port
                const unsigned long long* qr = c_q2 + (dc * DC + r) * 32 + h * 16;
#pragma unroll
                for (int t2 = 0; t2 < 8; ++t2) {
                    unsigned long long qe = qr[t2];
                    unsigned long long qo = qr[8 + t2];
#pragma unroll
                    for (int a = 0; a < 4; ++a)
                        accE[a] = ffma2(xq[t2 + a], qe, accE[a]);
#pragma unroll
                    for (int a = 0; a < 5; ++a)
                        accO[a] = ffma2(xq[t2 + a], qo, accO[a]);
                }
            }
        }
        // tail columns 2048..2079: squared sums by warp 0 (register-resident)
        if (tid < 32) {
#pragma unroll
            for (int r = 0; r < DC; ++r) {
                float v = tb[r * RSTRIDE + tailpc];
                tacc = fmaf(v, v, tacc);
            }
        }
        __syncthreads();
    }

    // ---- write per-column squared sums once ----
    {
        int c0 = 8 * tid;
        int pc = c0 + ((c0 >> 5) << 2);
        ulonglong2 a; a.x = sq[0]; a.y = sq[1];
        ulonglong2 b; b.x = sq[2]; b.y = sq[3];
        *(ulonglong2*)(s_sh + pc) = a;
        *(ulonglong2*)(s_sh + pc + 4) = b;
    }
    if (tid < 32) s_sh[tailpc] = tacc;
    __syncthreads();

    // ---- assemble distances ----
    float sv[KPOS + MLEN];
#pragma unroll
    for (int i = 0; i < 10; ++i) {
        int g = 2 * tid + i;
        int pf = (g + (g >> 3)) << 2;
        float4 f = *(const float4*)(s_sh + pf);
        sv[4 * i + 0] = f.x; sv[4 * i + 1] = f.y;
        sv[4 * i + 2] = f.z; sv[4 * i + 3] = f.w;
    }
    float qx[KPOS];
    {
        float el[4], eh[4], ol[5], oh[5];
#pragma unroll
        for (int a = 0; a < 4; ++a) up2(accE[a], el[a], eh[a]);
#pragma unroll
        for (int a = 0; a < 5; ++a) up2(accO[a], ol[a], oh[a]);
#pragma unroll
        for (int a = 0; a < 4; ++a) {
            qx[2 * a]     = el[a] + oh[a];
            qx[2 * a + 1] = eh[a] + ol[a + 1];
        }
    }
    float dist[KPOS];
    {
        float w = 0.f;
#pragma unroll
        for (int j = 0; j < MLEN; ++j) w += sv[j];
        dist[0] = w - 2.f * qx[0];
#pragma unroll
        for (int k = 1; k < KPOS; ++k) {
            w += sv[k - 1 + MLEN] - sv[k - 1];
            dist[k] = w - 2.f * qx[k];
        }
    }

    // ---- segment assignment + atomic min ----
    int p0 = pStart + tid * KPOS;
    if (p0 < P) {
        int lo = 0, hi = n_seg - 1;
        while (lo < hi) {
            int mid = (lo + hi + 1) >> 1;
            if (__ldg(&cum[mid]) <= p0) lo = mid; else hi = mid - 1;
        }
        int seg = lo;
        int nxt = __ldg(&cum[seg + 1]);
        unsigned lm = 0xFFFFFFFFu;
#pragma unroll
        for (int k = 0; k < KPOS; ++k) {
            int p = p0 + k;
            if (p >= P) break;
            while (p >= nxt) {
                if (lm != 0xFFFFFFFFu) atomicMin(&g_mins[seg], lm);
                lm = 0xFFFFFFFFu;
                ++seg;
                nxt = __ldg(&cum[seg + 1]);
            }
            if (p + MLEN <= nxt) lm = min(lm, enc_f(dist[k]));
        }
        if (lm != 0xFFFFFFFFu) atomicMin(&g_mins[seg], lm);
    }

    // ---- fused finalize: last block does min/max + scale + linear ----
    __threadfence();
    __syncthreads();
    __shared__ int s_last;
    __shared__ float rlo[8], rhi[8];
    if (tid == 0) s_last = (atomicAdd(&g_done, 1) == (int)gridDim.x - 1);
    __syncthreads();
    if (s_last) {
        __threadfence();
        float flo = 3.0e38f, fhi = -3.0e38f;
        for (int i = tid; i < n_seg; i += TPB) {
            unsigned u = g_mins[i];
            float v = (u == 0xFFFFFFFFu) ? 1.0e30f : dec_f(u);
            flo = fminf(flo, v);
            fhi = fmaxf(fhi, v);
        }
#pragma unroll
        for (int o = 16; o; o >>= 1) {
            flo = fminf(flo, __shfl_xor_sync(0xFFFFFFFFu, flo, o));
            fhi = fmaxf(fhi, __shfl_xor_sync(0xFFFFFFFFu, fhi, o));
        }
        if ((tid & 31) == 0) { rlo[tid >> 5] = flo; rhi[tid >> 5] = fhi; }
        __syncthreads();
        if (tid < 32) {
            flo = (tid < 8) ? rlo[tid] : 3.0e38f;
            fhi = (tid < 8) ? rhi[tid] : -3.0e38f;
#pragma unroll
            for (int o = 4; o; o >>= 1) {
                flo = fminf(flo, __shfl_xor_sync(0xFFFFFFFFu, flo, o));
                fhi = fmaxf(fhi, __shfl_xor_sync(0xFFFFFFFFu, fhi, o));
            }
            if (tid == 0) { rlo[0] = flo; rhi[0] = fhi; }
        }
        __syncthreads();
        flo = rlo[0]; fhi = rhi[0];
        const float denom = fhi - flo + 1e-16f;
        const float w0 = lin_w[0], w1 = lin_w[1];
        const float b0 = lin_b[0], b1 = lin_b[1];
        for (int i = tid; i < n_seg; i += TPB) {
            unsigned u = g_mins[i];
            float v = (u == 0xFFFFFFFFu) ? 1.0e30f : dec_f(u);
            float sc = (v - flo) / denom;
            out[2 * i + 0] = fmaf(sc, w0, b0);
            out[2 * i + 1] = fmaf(sc, w1, b1);
        }
        if (tid == 0) g_done = 0;
    }
}

extern "C" void kernel_launch(void* const* d_in, const int* in_sizes, int n_in,
                              void* d_out, int out_size)
{
    const float* X     = (const float*)d_in[0];
    const float* query = (const float*)d_in[1];
    const float* lin_w = (const float*)d_in[2];
    const float* lin_b = (const float*)d_in[3];
    const int*   cum   = (const int*)d_in[4];
    float* out = (float*)d_out;

    const int T     = in_sizes[0] / DIM;
    const int n_seg = in_sizes[4] - 1;
    const int P     = T - MLEN + 1;

    cudaFuncSetAttribute(shapelet_main_kernel,
                         cudaFuncAttributeMaxDynamicSharedMemorySize, SM_TOTAL);

    // stage duplicated q pairs, then copy into constant bank (D2D, capture-safe)
    prep_q_kernel<<<(DIM * MLEN + 255) / 256, 256>>>(query);
    void* q2_addr = nullptr;
    cudaGetSymbolAddress(&q2_addr, g_q2);
    cudaMemcpyToSymbolAsync(c_q2, q2_addr, DIM * MLEN * sizeof(unsigned long long),
                            0, cudaMemcpyDeviceToDevice, 0);

    init_mins_kernel<<<(n_seg + 255) / 256, 256>>>(n_seg);

    const int nblocks = (P + TILE_POS - 1) / TILE_POS;
    shapelet_main_kernel<<<nblocks, TPB, SM_TOTAL>>>(
        X, cum, lin_w, lin_b, out, T, n_seg, P);
}

// round 14
// speedup vs baseline: 1.0482x; 1.0482x over previous
#include <cuda_runtime.h>
#include <stdint.h>

// Problem constants: D=64, M=32, output fp32 [n_seg, 2]
#define DIM      64
#define MLEN     32
#define NGROUP   4                      // D split into 4 groups of 16 rows
#define GROWS    (DIM / NGROUP)         // 16 d-rows per block
#define DC       2                      // d-rows per chunk
#define NCHUNK   (GROWS / DC)           // 8 chunks per block
#define TPB      256
#define KPOS     8                      // positions per thread
#define TILE_POS (TPB * KPOS)           // 2048 window starts per block
#define TILE_COLS (TILE_POS + MLEN)     // 2080 columns per tile row
#define NGRAN    (TILE_COLS / 4)        // 520 16B granules per row
// pad 1 granule (16B) per 8 granules (128B): conflict-free for stride-2-granule lanes
#define RSTRIDE  (TILE_COLS + (TILE_COLS / 32) * 4)   // 2340 floats

#define MAX_SEG  8192
#define P_PAD    2101248                // padded stripe stride (>= tiles*2048)

__device__ unsigned g_mins[MAX_SEG];
__device__ int g_done;
__device__ float g_part[NGROUP * P_PAD];   // per-group partial dist stripes (33.6MB)
__constant__ float c_q[DIM * MLEN];        // query on the constant port

// order-preserving float -> uint mapping (ascending)
__device__ __forceinline__ unsigned enc_f(float f) {
    int b = __float_as_int(f);
    return (unsigned)(b >= 0 ? (b | 0x80000000) : ~b);
}
__device__ __forceinline__ float dec_f(unsigned u) {
    int b = (u & 0x80000000u) ? (int)(u & 0x7FFFFFFFu) : ~(int)u;
    return __int_as_float(b);
}

__device__ __forceinline__ unsigned long long ffma2(unsigned long long a,
                                                    unsigned long long b,
                                                    unsigned long long c) {
    unsigned long long d;
    asm("fma.rn.f32x2 %0, %1, %2, %3;" : "=l"(d) : "l"(a), "l"(b), "l"(c));
    return d;
}
__device__ __forceinline__ unsigned long long pk2(float lo, float hi) {
    unsigned long long r;
    asm("mov.b64 %0, {%1, %2};" : "=l"(r) : "f"(lo), "f"(hi));
    return r;
}
__device__ __forceinline__ void up2(unsigned long long v, float& a, float& b) {
    asm("mov.b64 {%0, %1}, %2;" : "=f"(a), "=f"(b) : "l"(v));
}
__device__ __forceinline__ void cpa16(uint32_t dst, const void* src) {
    asm volatile("cp.async.cg.shared.global [%0], [%1], 16;" :: "r"(dst), "l"(src));
}
__device__ __forceinline__ void cpa_commit() {
    asm volatile("cp.async.commit_group;" ::: "memory");
}
__device__ __forceinline__ void cpa_wait1() {
    asm volatile("cp.async.wait_group 1;" ::: "memory");
}

// smem float layout:
//   tile : [2][DC][RSTRIDE]          floats 0 .. 9360
//   s_sh : [RSTRIDE]                 floats 9360 .. 11700
#define SM_SSH   (2 * DC * RSTRIDE)
#define SM_TOTAL ((SM_SSH + RSTRIDE) * 4)

// Main kernel: grid (tiles, NGROUP). Block (bx, g) computes the partial
// dist contribution of d-rows [g*16, g*16+16) for positions in tile bx,
// writing plain coalesced STG into stripe g (no atomics: deterministic).
// Blocks (bx<32, g==0) also initialize g_mins for the segmin kernel.
__global__ __launch_bounds__(TPB, 4) void shapelet_main_kernel(
    const float* __restrict__ X,      // [DIM, T]
    int T, int n_seg, int P)
{
    extern __shared__ float sh[];
    float* s_sh = sh + SM_SSH;
    const uint32_t sbase = (uint32_t)__cvta_generic_to_shared(sh);

    const int tid    = threadIdx.x;
    const int g      = blockIdx.y;
    const int pStart = blockIdx.x * TILE_POS;
    const bool inb   = (pStart + TILE_COLS <= T);
    const int dBase  = g * GROWS;

    // fold g_mins init into the main kernel (consumed only by segmin kernel)
    if (g == 0 && blockIdx.x < 32) {
        for (int i = blockIdx.x * TPB + tid; i < n_seg; i += 32 * TPB)
            g_mins[i] = 0xFFFFFFFFu;
    }

    unsigned long long accE[4], accO[5], sq[4];
#pragma unroll
    for (int a = 0; a < 4; ++a) { accE[a] = 0ull; sq[a] = 0ull; }
#pragma unroll
    for (int a = 0; a < 5; ++a) accO[a] = 0ull;
    float tacc = 0.f;                       // tail col (warp 0 only)
    const int tailpc = (2048 + tid) + (((2048 + tid) >> 5) << 2);

    // ---- prefetch one chunk into buffer b ----
    auto prefetch = [&](int dc, int b) {
#pragma unroll
        for (int r = 0; r < DC; ++r) {
            const float* src = X + (size_t)(dBase + dc * DC + r) * T + pStart;
            uint32_t drow = sbase + (uint32_t)((b * DC + r) * RSTRIDE) * 4u;
            float* growp = sh + (b * DC + r) * RSTRIDE;
            if (inb) {
                for (int gi = tid; gi < NGRAN; gi += TPB) {
                    int pf = (gi + (gi >> 3)) << 2;
                    cpa16(drow + (uint32_t)pf * 4u, src + (gi << 2));
                }
            } else {
                for (int gi = tid; gi < NGRAN; gi += TPB) {
                    int pf = (gi + (gi >> 3)) << 2;
                    int gc = pStart + (gi << 2);
                    if (gc + 4 <= T) {
                        cpa16(drow + (uint32_t)pf * 4u, src + (gi << 2));
                    } else {
                        float4 z;
                        z.x = (gc + 0 < T) ? src[(gi << 2) + 0] : 0.f;
                        z.y = (gc + 1 < T) ? src[(gi << 2) + 1] : 0.f;
                        z.z = (gc + 2 < T) ? src[(gi << 2) + 2] : 0.f;
                        z.w = (gc + 3 < T) ? src[(gi << 2) + 3] : 0.f;
                        *(float4*)(growp + pf) = z;
                    }
                }
            }
        }
    };

    prefetch(0, 0);
    cpa_commit();

#pragma unroll 1
    for (int dc = 0; dc < NCHUNK; ++dc) {
        const int par = dc & 1;
        if (dc + 1 < NCHUNK) prefetch(dc + 1, (dc + 1) & 1);
        cpa_commit();
        cpa_wait1();
        __syncthreads();

        const float* tb = sh + par * DC * RSTRIDE;
#pragma unroll
        for (int r = 0; r < DC; ++r) {
            const float* rowp = tb + r * RSTRIDE;
#pragma unroll
            for (int h = 0; h < 2; ++h) {
                unsigned long long xq[12];
#pragma unroll
                for (int i = 0; i < 6; ++i) {
                    int gg = 2 * tid + 4 * h + i;
                    int pf = (gg + (gg >> 3)) << 2;
                    ulonglong2 vv = *(const ulonglong2*)(rowp + pf);
                    xq[2 * i] = vv.x; xq[2 * i + 1] = vv.y;
                }
                if (h == 0) {
#pragma unroll
                    for (int j = 0; j < 4; ++j)
                        sq[j] = ffma2(xq[j], xq[j], sq[j]);
                }
                // query taps from the constant port
                const float* qrow = c_q + (dBase + dc * DC + r) * MLEN + 16 * h;
#pragma unroll
                for (int t2 = 0; t2 < 8; ++t2) {
                    float qev = qrow[2 * t2];
                    float qov = qrow[2 * t2 + 1];
                    unsigned long long qe = pk2(qev, qev);
                    unsigned long long qo = pk2(qov, qov);
#pragma unroll
                    for (int a = 0; a < 4; ++a)
                        accE[a] = ffma2(xq[t2 + a], qe, accE[a]);
#pragma unroll
                    for (int a = 0; a < 5; ++a)
                        accO[a] = ffma2(xq[t2 + a], qo, accO[a]);
                }
            }
        }
        // tail columns 2048..2079: squared sums by warp 0 (register-resident)
        if (tid < 32) {
#pragma unroll
            for (int r = 0; r < DC; ++r) {
                float v = tb[r * RSTRIDE + tailpc];
                tacc = fmaf(v, v, tacc);
            }
        }
        __syncthreads();
    }

    // ---- write per-column squared sums once ----
    {
        int c0 = 8 * tid;
        int pc = c0 + ((c0 >> 5) << 2);
        ulonglong2 a; a.x = sq[0]; a.y = sq[1];
        ulonglong2 b; b.x = sq[2]; b.y = sq[3];
        *(ulonglong2*)(s_sh + pc) = a;
        *(ulonglong2*)(s_sh + pc + 4) = b;
    }
    if (tid < 32) s_sh[tailpc] = tacc;
    __syncthreads();

    // ---- assemble partial distances ----
    float sv[KPOS + MLEN];
#pragma unroll
    for (int i = 0; i < 10; ++i) {
        int gg = 2 * tid + i;
        int pf = (gg + (gg >> 3)) << 2;
        float4 f = *(const float4*)(s_sh + pf);
        sv[4 * i + 0] = f.x; sv[4 * i + 1] = f.y;
        sv[4 * i + 2] = f.z; sv[4 * i + 3] = f.w;
    }
    float qx[KPOS];
    {
        float el[4], eh[4], ol[5], oh[5];
#pragma unroll
        for (int a = 0; a < 4; ++a) up2(accE[a], el[a], eh[a]);
#pragma unroll
        for (int a = 0; a < 5; ++a) up2(accO[a], ol[a], oh[a]);
#pragma unroll
        for (int a = 0; a < 4; ++a) {
            qx[2 * a]     = el[a] + oh[a];
            qx[2 * a + 1] = eh[a] + ol[a + 1];
        }
    }
    float dist[KPOS];
    {
        float w = 0.f;
#pragma unroll
        for (int j = 0; j < MLEN; ++j) w += sv[j];
        dist[0] = w - 2.f * qx[0];
#pragma unroll
        for (int k = 1; k < KPOS; ++k) {
            w += sv[k - 1 + MLEN] - sv[k - 1];
            dist[k] = w - 2.f * qx[k];
        }
    }

    // ---- plain coalesced store of the partial dist stripe ----
    {
        int p0 = pStart + tid * KPOS;
        float* dst = g_part + (size_t)g * P_PAD + p0;
        float4 a; a.x = dist[0]; a.y = dist[1]; a.z = dist[2]; a.w = dist[3];
        float4 b; b.x = dist[4]; b.y = dist[5]; b.z = dist[6]; b.w = dist[7];
        *(float4*)(dst + 0) = a;
        *(float4*)(dst + 4) = b;
    }
}

// Reduce kernel: sum the 4 partial stripes, segment search, atomicMin,
// then the last block does min/max + scale + linear (fused finalize).
__global__ __launch_bounds__(TPB) void segmin_kernel(
    const int*   __restrict__ cum,    // [n_seg+1]
    const float* __restrict__ lin_w,
    const float* __restrict__ lin_b,
    float* __restrict__ out,
    int n_seg, int P)
{
    const int tid = threadIdx.x;
    const int p0  = blockIdx.x * TILE_POS + tid * KPOS;

    float dist[KPOS];
#pragma unroll
    for (int k = 0; k < KPOS; ++k) dist[k] = 0.f;
#pragma unroll
    for (int g = 0; g < NGROUP; ++g) {
        const float* src = g_part + (size_t)g * P_PAD + p0;
        float4 a = *(const float4*)(src + 0);
        float4 b = *(const float4*)(src + 4);
        dist[0] += a.x; dist[1] += a.y; dist[2] += a.z; dist[3] += a.w;
        dist[4] += b.x; dist[5] += b.y; dist[6] += b.z; dist[7] += b.w;
    }

    if (p0 < P) {
        int lo = 0, hi = n_seg - 1;
        while (lo < hi) {
            int mid = (lo + hi + 1) >> 1;
            if (__ldg(&cum[mid]) <= p0) lo = mid; else hi = mid - 1;
        }
        int seg = lo;
        int nxt = __ldg(&cum[seg + 1]);
        unsigned lm = 0xFFFFFFFFu;
#pragma unroll
        for (int k = 0; k < KPOS; ++k) {
            int p = p0 + k;
            if (p >= P) break;
            while (p >= nxt) {
                if (lm != 0xFFFFFFFFu) atomicMin(&g_mins[seg], lm);
                lm = 0xFFFFFFFFu;
                ++seg;
                nxt = __ldg(&cum[seg + 1]);
            }
            if (p + MLEN <= nxt) lm = min(lm, enc_f(dist[k]));
        }
        if (lm != 0xFFFFFFFFu) atomicMin(&g_mins[seg], lm);
    }

    // ---- fused finalize: last block does min/max + scale + linear ----
    __threadfence();
    __syncthreads();
    __shared__ int s_last;
    __shared__ float rlo[8], rhi[8];
    if (tid == 0) s_last = (atomicAdd(&g_done, 1) == (int)gridDim.x - 1);
    __syncthreads();
    if (s_last) {
        __threadfence();
        float flo = 3.0e38f, fhi = -3.0e38f;
        for (int i = tid; i < n_seg; i += TPB) {
            unsigned u = g_mins[i];
            float v = (u == 0xFFFFFFFFu) ? 1.0e30f : dec_f(u);
            flo = fminf(flo, v);
            fhi = fmaxf(fhi, v);
        }
#pragma unroll
        for (int o = 16; o; o >>= 1) {
            flo = fminf(flo, __shfl_xor_sync(0xFFFFFFFFu, flo, o));
            fhi = fmaxf(fhi, __shfl_xor_sync(0xFFFFFFFFu, fhi, o));
        }
        if ((tid & 31) == 0) { rlo[tid >> 5] = flo; rhi[tid >> 5] = fhi; }
        __syncthreads();
        if (tid < 32) {
            flo = (tid < 8) ? rlo[tid] : 3.0e38f;
            fhi = (tid < 8) ? rhi[tid] : -3.0e38f;
#pragma unroll
            for (int o = 4; o; o >>= 1) {
                flo = fminf(flo, __shfl_xor_sync(0xFFFFFFFFu, flo, o));
                fhi = fmaxf(fhi, __shfl_xor_sync(0xFFFFFFFFu, fhi, o));
            }
            if (tid == 0) { rlo[0] = flo; rhi[0] = fhi; }
        }
        __syncthreads();
        flo = rlo[0]; fhi = rhi[0];
        const float denom = fhi - flo + 1e-16f;
        const float w0 = lin_w[0], w1 = lin_w[1];
        const float b0 = lin_b[0], b1 = lin_b[1];
        for (int i = tid; i < n_seg; i += TPB) {
            unsigned u = g_mins[i];
            float v = (u == 0xFFFFFFFFu) ? 1.0e30f : dec_f(u);
            float sc = (v - flo) / denom;
            out[2 * i + 0] = fmaf(sc, w0, b0);
            out[2 * i + 1] = fmaf(sc, w1, b1);
        }
        if (tid == 0) g_done = 0;
    }
}

extern "C" void kernel_launch(void* const* d_in, const int* in_sizes, int n_in,
                              void* d_out, int out_size)
{
    const float* X     = (const float*)d_in[0];
    const float* query = (const float*)d_in[1];
    const float* lin_w = (const float*)d_in[2];
    const float* lin_b = (const float*)d_in[3];
    const int*   cum   = (const int*)d_in[4];
    float* out = (float*)d_out;

    const int T     = in_sizes[0] / DIM;
    const int n_seg = in_sizes[4] - 1;
    const int P     = T - MLEN + 1;

    cudaFuncSetAttribute(shapelet_main_kernel,
                         cudaFuncAttributeMaxDynamicSharedMemorySize, SM_TOTAL);

    // stage query into constant memory (D2D async: graph-capturable)
    cudaMemcpyToSymbolAsync(c_q, query, DIM * MLEN * sizeof(float), 0,
                            cudaMemcpyDeviceToDevice, 0);

    const int nblocks = (P + TILE_POS - 1) / TILE_POS;
    shapelet_main_kernel<<<dim3(nblocks, NGROUP), TPB, SM_TOTAL>>>(X, T, n_seg, P);
    segmin_kernel<<<nblocks, TPB>>>(cum, lin_w, lin_b, out, n_seg, P);
}